// round 6
// baseline (speedup 1.0000x reference)
#include <cuda_runtime.h>
#include <math.h>

#define IMG_W 1024
#define IMG_H 1024
#define IMG_B 8
#define IMG_HW (IMG_H * IMG_W)

// ---------------------------------------------------------------------------
// Scratch buffers (allocation-free rule: __device__ globals)
// ---------------------------------------------------------------------------
__device__ float2 g_sm[(size_t)IMG_B * IMG_HW];        // smoothed (double-float)
__device__ float2 g_g2[(size_t)IMG_B * IMG_HW];        // grad^2 (double-float)
__device__ unsigned char g_bin[(size_t)IMG_B * IMG_HW];// direction bin 0..3
__device__ float g_sup[(size_t)IMG_B * IMG_HW];
__device__ float g_strong[(size_t)IMG_B * IMG_HW];
__device__ unsigned int g_min_bits;
__device__ unsigned int g_max_bits;

__device__ __forceinline__ int refl(int i, int n) {
    if (i < 0) i = -i;
    if (i >= n) i = 2 * n - 2 - i;
    return i;
}

__device__ __forceinline__ float sigm(float x) {
    return 1.0f / (1.0f + expf(-x));
}

// ---------------------------------------------------------------------------
// Double-float (compensated fp32) arithmetic — ~2^-48 relative error
// ---------------------------------------------------------------------------
struct DF { float h, l; };

__device__ __forceinline__ DF df_make(float h, float l) { DF r; r.h = h; r.l = l; return r; }

// exact product of two floats
__device__ __forceinline__ DF df_twoprod(float a, float b) {
    float p = a * b;
    float e = fmaf(a, b, -p);
    return df_make(p, e);
}

// Knuth TwoSum based df add, renormalized
__device__ __forceinline__ DF df_add(DF a, DF b) {
    float s  = a.h + b.h;
    float bp = s - a.h;
    float ap = s - bp;
    float eb = b.h - bp;
    float ea = a.h - ap;
    float e  = (ea + eb) + (a.l + b.l);
    float h  = s + e;
    float l  = e - (h - s);
    return df_make(h, l);
}

__device__ __forceinline__ DF df_neg(DF a)    { return df_make(-a.h, -a.l); }
__device__ __forceinline__ DF df_scale2(DF a) { return df_make(2.0f * a.h, 2.0f * a.l); } // exact

__device__ __forceinline__ DF df_sqr(DF a) {
    float p = a.h * a.h;
    float e = fmaf(a.h, a.h, -p);
    e = fmaf(2.0f * a.h, a.l, e);
    float h = p + e;
    float l = e - (h - p);
    return df_make(h, l);
}

__device__ __forceinline__ DF df_mul_df(DF a, DF b) {
    float p = a.h * b.h;
    float e = fmaf(a.h, b.h, -p);
    e = e + (a.h * b.l + a.l * b.h);
    float h = p + e;
    float l = e - (h - p);
    return df_make(h, l);
}

__device__ __forceinline__ bool df_lt(DF a, DF b) {
    return (a.h < b.h) || (a.h == b.h && a.l < b.l);
}
__device__ __forceinline__ bool df_gt(DF a, DF b) {
    return (a.h > b.h) || (a.h == b.h && a.l > b.l);
}
__device__ __forceinline__ DF df_abs(DF a) {
    bool neg = (a.h < 0.0f) || (a.h == 0.0f && a.l < 0.0f);
    return neg ? df_make(-a.h, -a.l) : a;
}
__device__ __forceinline__ bool df_pos(DF a) {
    return (a.h > 0.0f) || (a.h == 0.0f && a.l > 0.0f);
}

// ---------------------------------------------------------------------------
// Kernel 1: 5x5 Gaussian blur, reflect pad, double-float accumulation
// ---------------------------------------------------------------------------
__global__ __launch_bounds__(256) void gauss_kernel(const float* __restrict__ img) {
    const int x = blockIdx.x * 32 + threadIdx.x;
    const int y = blockIdx.y * 8 + threadIdx.y;
    const int b = blockIdx.z;
    const float* p = img + (size_t)b * IMG_HW;

    // 1D fp32 weights (correctly rounded); 2D weight = fp32 product w[i]*w[j],
    // matching the reference's fp32 outer product k = g[:,None]*g[None,:].
    const float w5[5] = {0.054488684549640294f, 0.24420134200323337f,
                         0.4026199468935272f,  0.24420134200323337f,
                         0.054488684549640294f};

    DF acc = df_make(0.0f, 0.0f);
    if (x >= 2 && x < IMG_W - 2 && y >= 2 && y < IMG_H - 2) {
#pragma unroll
        for (int dy = 0; dy < 5; dy++) {
            const float* row = p + (y + dy - 2) * IMG_W + (x - 2);
#pragma unroll
            for (int dx = 0; dx < 5; dx++)
                acc = df_add(acc, df_twoprod(w5[dy] * w5[dx], row[dx]));
        }
    } else {
#pragma unroll
        for (int dy = 0; dy < 5; dy++) {
            const int yy = refl(y + dy - 2, IMG_H);
#pragma unroll
            for (int dx = 0; dx < 5; dx++)
                acc = df_add(acc, df_twoprod(w5[dy] * w5[dx],
                                             p[yy * IMG_W + refl(x + dx - 2, IMG_W)]));
        }
    }
    g_sm[(size_t)b * IMG_HW + y * IMG_W + x] = make_float2(acc.h, acc.l);
}

// ---------------------------------------------------------------------------
// Kernel 2: Sobel (double-float) -> grad^2 (df) + direction bin code
// ---------------------------------------------------------------------------
__global__ __launch_bounds__(256) void sobel_kernel() {
    const int x = blockIdx.x * 32 + threadIdx.x;
    const int y = blockIdx.y * 8 + threadIdx.y;
    const int b = blockIdx.z;
    const float2* sm = g_sm + (size_t)b * IMG_HW;

    DF v[3][3];
    if (x >= 1 && x < IMG_W - 1 && y >= 1 && y < IMG_H - 1) {
#pragma unroll
        for (int dy = -1; dy <= 1; dy++)
#pragma unroll
            for (int dx = -1; dx <= 1; dx++) {
                float2 t = sm[(y + dy) * IMG_W + (x + dx)];
                v[dy + 1][dx + 1] = df_make(t.x, t.y);
            }
    } else {
#pragma unroll
        for (int dy = -1; dy <= 1; dy++) {
            const int yy = refl(y + dy, IMG_H);
#pragma unroll
            for (int dx = -1; dx <= 1; dx++) {
                float2 t = sm[yy * IMG_W + refl(x + dx, IMG_W)];
                v[dy + 1][dx + 1] = df_make(t.x, t.y);
            }
        }
    }

    // gx: kx = [[-1,0,1],[-2,0,2],[-1,0,1]] cross-correlation
    DF gx = df_add(df_add(df_add(v[0][2], df_neg(v[0][0])),
                          df_scale2(df_add(v[1][2], df_neg(v[1][0])))),
                   df_add(v[2][2], df_neg(v[2][0])));
    // gy: ky = [[1,2,1],[0,0,0],[-1,-2,-1]]
    DF gy = df_add(df_add(df_add(v[0][0], df_scale2(v[0][1])), v[0][2]),
                   df_neg(df_add(df_add(v[2][0], df_scale2(v[2][1])), v[2][2])));

    DF g2 = df_add(df_sqr(gx), df_sqr(gy));

    // Direction bins via exact ratio tests (equivalent to atan2-degree bins):
    //   bin 0: d in [0,22.5) U [157.5,180)  -> E/W
    //   bin 1: d in [22.5,67.5)             -> SW/NE  (gx,gy same sign)
    //   bin 2: d in [67.5,112.5)            -> N/S
    //   bin 3: d in [112.5,157.5)           -> SE/NW
    const double T1d = 0.41421356237309503;  // tan(22.5 deg)
    const double T2d = 2.414213562373095;    // tan(67.5 deg)
    const DF T1 = df_make((float)T1d, (float)(T1d - (double)(float)T1d));
    const DF T2 = df_make((float)T2d, (float)(T2d - (double)(float)T2d));

    DF ax = df_abs(gx), ay = df_abs(gy);
    unsigned char bin;
    if (df_lt(ay, df_mul_df(T1, ax)))       bin = 0;
    else if (!df_lt(ay, df_mul_df(T2, ax))) bin = 2;   // ay >= T2*ax
    else                                    bin = (df_pos(gx) == df_pos(gy)) ? 1 : 3;

    const size_t idx = (size_t)b * IMG_HW + y * IMG_W + x;
    g_g2[idx]  = make_float2(g2.h, g2.l);
    g_bin[idx] = bin;
}

// ---------------------------------------------------------------------------
// Kernel 3: init reduction scalars
// ---------------------------------------------------------------------------
__global__ void init_minmax_kernel() {
    g_min_bits = 0x7F800000u;  // +inf
    g_max_bits = 0u;           // 0.0f (sup >= 0)
}

// ---------------------------------------------------------------------------
// Kernel 4: non-max suppression (exact df compares on grad^2) + min/max reduce
// ---------------------------------------------------------------------------
__global__ __launch_bounds__(256) void nms_kernel() {
    const int x = blockIdx.x * 32 + threadIdx.x;
    const int y = blockIdx.y * 8 + threadIdx.y;
    const int b = blockIdx.z;
    const float2* gq = g_g2 + (size_t)b * IMG_HW;

    DF nb[3][3];
    if (x >= 1 && x < IMG_W - 1 && y >= 1 && y < IMG_H - 1) {
#pragma unroll
        for (int dy = -1; dy <= 1; dy++)
#pragma unroll
            for (int dx = -1; dx <= 1; dx++) {
                float2 t = gq[(y + dy) * IMG_W + (x + dx)];
                nb[dy + 1][dx + 1] = df_make(t.x, t.y);
            }
    } else {
#pragma unroll
        for (int dy = -1; dy <= 1; dy++) {
            const int yy = refl(y + dy, IMG_H);
#pragma unroll
            for (int dx = -1; dx <= 1; dx++) {
                float2 t = gq[yy * IMG_W + refl(x + dx, IMG_W)];
                nb[dy + 1][dx + 1] = df_make(t.x, t.y);
            }
        }
    }

    const size_t idx = (size_t)b * IMG_HW + y * IMG_W + x;
    const DF c = nb[1][1];
    const int bin = g_bin[idx];

    bool keep;
    if (bin == 0)      keep = df_gt(c, nb[1][2]) && df_gt(c, nb[1][0]);  // e, w
    else if (bin == 2) keep = df_gt(c, nb[0][1]) && df_gt(c, nb[2][1]);  // n, s
    else if (bin == 1) keep = df_gt(c, nb[2][0]) && df_gt(c, nb[0][2]);  // sw, ne
    else               keep = df_gt(c, nb[2][2]) && df_gt(c, nb[0][0]);  // se, nw

    float sup = 0.0f;
    if (keep) {
        float r = sqrtf(c.h);
        if (c.h > 1.1754944e-38f) {  // Newton step toward sqrt(c.h + c.l)
            float resid = fmaf(-r, r, c.h) + c.l;
            r = fmaf(resid, 0.5f / r, r);
        }
        sup = r;
    }
    g_sup[idx] = sup;

    // fused block min/max reduce (sup >= 0 -> uint order == float order)
    float vmin = sup, vmax = sup;
#pragma unroll
    for (int off = 16; off > 0; off >>= 1) {
        vmin = fminf(vmin, __shfl_xor_sync(0xFFFFFFFF, vmin, off));
        vmax = fmaxf(vmax, __shfl_xor_sync(0xFFFFFFFF, vmax, off));
    }
    __shared__ float smin[8], smax[8];
    const int tid = threadIdx.y * 32 + threadIdx.x;
    const int wid = tid >> 5;
    if ((tid & 31) == 0) { smin[wid] = vmin; smax[wid] = vmax; }
    __syncthreads();
    if (tid == 0) {
        float bmin = smin[0], bmax = smax[0];
#pragma unroll
        for (int i = 1; i < 8; i++) {
            bmin = fminf(bmin, smin[i]);
            bmax = fmaxf(bmax, smax[i]);
        }
        atomicMin(&g_min_bits, __float_as_uint(bmin));
        atomicMax(&g_max_bits, __float_as_uint(bmax));
    }
}

// ---------------------------------------------------------------------------
// Kernel 5: strong = sigmoid(100*(sup - high))
// ---------------------------------------------------------------------------
__global__ __launch_bounds__(256) void strong_kernel() {
    const size_t idx = (size_t)blockIdx.x * 256 + threadIdx.x;
    const float mn = __uint_as_float(g_min_bits);
    const float mx = __uint_as_float(g_max_bits);
    const float high = mn + (mx - mn) * 0.25f;
    g_strong[idx] = sigm(100.0f * (g_sup[idx] - high));
}

// ---------------------------------------------------------------------------
// Kernel 6: final mask = strong + weak * sigmoid(100*(has_strong - 0.5))
// ---------------------------------------------------------------------------
__global__ __launch_bounds__(256) void final_kernel(float* __restrict__ out) {
    const int x = blockIdx.x * 32 + threadIdx.x;
    const int y = blockIdx.y * 8 + threadIdx.y;
    const int b = blockIdx.z;
    const float* st = g_strong + (size_t)b * IMG_HW;
    const float* su = g_sup + (size_t)b * IMG_HW;

    const float mn = __uint_as_float(g_min_bits);
    const float mx = __uint_as_float(g_max_bits);
    const float low = mn + (mx - mn) * 0.1f;

    const size_t idx = (size_t)y * IMG_W + x;
    const float s_c = st[idx];
    const float sup = su[idx];
    const float weak = sigm(100.0f * (sup - low)) * (1.0f - s_c);

    float hs = 0.0f;
    if (x >= 1 && x < IMG_W - 1 && y >= 1 && y < IMG_H - 1) {
#pragma unroll
        for (int dy = -1; dy <= 1; dy++)
#pragma unroll
            for (int dx = -1; dx <= 1; dx++)
                hs += st[(y + dy) * IMG_W + (x + dx)];
    } else {
#pragma unroll
        for (int dy = -1; dy <= 1; dy++) {
            const int yy = refl(y + dy, IMG_H);
#pragma unroll
            for (int dx = -1; dx <= 1; dx++)
                hs += st[yy * IMG_W + refl(x + dx, IMG_W)];
        }
    }
    out[(size_t)b * IMG_HW + idx] = s_c + weak * sigm(100.0f * (hs - 0.5f));
}

// ---------------------------------------------------------------------------
extern "C" void kernel_launch(void* const* d_in, const int* in_sizes, int n_in,
                              void* d_out, int out_size) {
    const float* image = (const float*)d_in[0];
    float* out = (float*)d_out;

    dim3 blk(32, 8, 1);
    dim3 grd(IMG_W / 32, IMG_H / 8, IMG_B);

    gauss_kernel<<<grd, blk>>>(image);
    sobel_kernel<<<grd, blk>>>();
    init_minmax_kernel<<<1, 1>>>();
    nms_kernel<<<grd, blk>>>();
    strong_kernel<<<((size_t)IMG_B * IMG_HW) / 256, 256>>>();
    final_kernel<<<grd, blk>>>(out);
}